// round 2
// baseline (speedup 1.0000x reference)
#include <cuda_runtime.h>

#define B_ 8
#define T_ 128
#define S_ 512
#define E_ 512
#define D_ 512

// ---- scratch (no allocs allowed) ----
__device__ float g_hp[B_*T_*D_];     // hidden @ W_h^T + b_attn
__device__ float g_ep[B_*S_*D_];     // encoder @ W_e^T
__device__ float g_en[B_*T_*S_];     // energies

__device__ __forceinline__ float tanh_fast(float x){
    float r; asm("tanh.approx.f32 %0, %1;" : "=f"(r) : "f"(x)); return r;
}

// ---------------------------------------------------------------------------
// C[n,j] = act( sum_d A[n,d] * B[j,d] + bias[j] )   (NT GEMM, both K-contig)
// A is split: d < splitK -> A0[n*lda + d]; d >= splitK -> A1[n*lda + (d-splitK)]
// ---------------------------------------------------------------------------
__global__ void gemm_nt_kernel(const float* __restrict__ A0,
                               const float* __restrict__ A1,
                               int splitK, int lda,
                               const float* __restrict__ Bm, int ldb,
                               const float* __restrict__ bias,
                               float* __restrict__ C, int ldc,
                               int Kd, int act)
{
    __shared__ __align__(16) float As[16][68];
    __shared__ __align__(16) float Bs[16][68];
    int tid = threadIdx.x;
    int m0 = blockIdx.x * 64;
    int n0 = blockIdx.y * 64;
    int tx = tid & 15, ty = tid >> 4;
    int lrow = tid >> 2;              // 0..63
    int lcol = (tid & 3) << 2;        // 0,4,8,12
    float acc[4][4] = {};
    for (int k0 = 0; k0 < Kd; k0 += 16) {
        int kk = k0 + lcol;
        const float* ap = (kk < splitK) ? (A0 + (size_t)(m0 + lrow) * lda + kk)
                                        : (A1 + (size_t)(m0 + lrow) * lda + (kk - splitK));
        float4 av = *(const float4*)ap;
        As[lcol+0][lrow]=av.x; As[lcol+1][lrow]=av.y;
        As[lcol+2][lrow]=av.z; As[lcol+3][lrow]=av.w;
        float4 bv = *(const float4*)(Bm + (size_t)(n0 + lrow) * ldb + kk);
        Bs[lcol+0][lrow]=bv.x; Bs[lcol+1][lrow]=bv.y;
        Bs[lcol+2][lrow]=bv.z; Bs[lcol+3][lrow]=bv.w;
        __syncthreads();
        #pragma unroll
        for (int k = 0; k < 16; k++) {
            float4 a = *(const float4*)&As[k][ty<<2];
            float4 b = *(const float4*)&Bs[k][tx<<2];
            float ar[4] = {a.x,a.y,a.z,a.w};
            float br[4] = {b.x,b.y,b.z,b.w};
            #pragma unroll
            for (int i = 0; i < 4; i++)
                #pragma unroll
                for (int j = 0; j < 4; j++)
                    acc[i][j] = fmaf(ar[i], br[j], acc[i][j]);
        }
        __syncthreads();
    }
    #pragma unroll
    for (int i = 0; i < 4; i++) {
        int row = m0 + (ty<<2) + i;
        #pragma unroll
        for (int j = 0; j < 4; j++) {
            int col = n0 + (tx<<2) + j;
            float v = acc[i][j];
            if (bias) v += bias[col];
            if (act)  v = tanh_fast(v);
            C[(size_t)row * ldc + col] = v;
        }
    }
}

// ---------------------------------------------------------------------------
// Batched NN GEMM: C[b][m,n] = sum_s A[b][m,s] * B[b][s,n]
// 256 threads, 64x64 tile, kTile=16. One float4 per thread per operand tile.
// ---------------------------------------------------------------------------
__global__ void gemm_nn_kernel(const float* __restrict__ A, int sAb, int lda,
                               const float* __restrict__ Bm, int sBb, int ldb,
                               float* __restrict__ C, int sCb, int ldc,
                               int Kd)
{
    int b = blockIdx.z;
    const float* Ab = A  + (size_t)b * sAb;
    const float* Bb = Bm + (size_t)b * sBb;
    float*       Cb = C  + (size_t)b * sCb;
    __shared__ __align__(16) float As[16][68];
    __shared__ __align__(16) float Bs[16][68];
    int tid = threadIdx.x;
    int m0 = blockIdx.x * 64, n0 = blockIdx.y * 64;
    int tx = tid & 15, ty = tid >> 4;
    int arow = tid >> 2, acol = (tid & 3) << 2;   // A: 64 rows x 16 k
    int brow = tid >> 4, bcol = (tid & 15) << 2;  // B: 16 k-rows x 64 cols
    float acc[4][4] = {};
    for (int k0 = 0; k0 < Kd; k0 += 16) {
        float4 av = *(const float4*)(Ab + (size_t)(m0 + arow) * lda + k0 + acol);
        As[acol+0][arow]=av.x; As[acol+1][arow]=av.y;
        As[acol+2][arow]=av.z; As[acol+3][arow]=av.w;
        float4 bv = *(const float4*)(Bb + (size_t)(k0 + brow) * ldb + n0 + bcol);
        *(float4*)&Bs[brow][bcol] = bv;
        __syncthreads();
        #pragma unroll
        for (int k = 0; k < 16; k++) {
            float4 a  = *(const float4*)&As[k][ty<<2];
            float4 b2 = *(const float4*)&Bs[k][tx<<2];
            float ar[4] = {a.x,a.y,a.z,a.w};
            float br[4] = {b2.x,b2.y,b2.z,b2.w};
            #pragma unroll
            for (int i = 0; i < 4; i++)
                #pragma unroll
                for (int j = 0; j < 4; j++)
                    acc[i][j] = fmaf(ar[i], br[j], acc[i][j]);
        }
        __syncthreads();
    }
    #pragma unroll
    for (int i = 0; i < 4; i++) {
        int row = m0 + (ty<<2) + i;
        #pragma unroll
        for (int j = 0; j < 4; j++)
            Cb[(size_t)row * ldc + n0 + (tx<<2) + j] = acc[i][j];
    }
}

// ---------------------------------------------------------------------------
// energies[b,t,s] = ( sum_k W_v[k]*tanh(hp[b,t,k] + ep[b,s,k]) + b_v ) * m[b,s]
// Block tile: 16 t x 64 s, 256 threads, 2x2 per thread.  MUFU-bound by design.
// ---------------------------------------------------------------------------
__global__ void energies_kernel(const float* __restrict__ hp,
                                const float* __restrict__ ep,
                                const float* __restrict__ wv,
                                const float* __restrict__ bv,
                                const float* __restrict__ mask,
                                float* __restrict__ en)
{
    __shared__ __align__(16) float hps[32][17];
    __shared__ __align__(16) float eps[32][65];
    __shared__ float wvs[32];
    int b = blockIdx.z, t0 = blockIdx.y * 16, s0 = blockIdx.x * 64;
    int tid = threadIdx.x;
    int sx = tid & 31, ty = tid >> 5;           // ty 0..7
    const float* hpb = hp + (size_t)(b*T_ + t0) * D_;
    const float* epb = ep + (size_t)(b*S_ + s0) * D_;
    float a00=0.f, a01=0.f, a10=0.f, a11=0.f;
    int ht = tid >> 4, hk = (tid & 15) << 1;    // hp: 16 rows x 32 k, 2 floats/thr
    int es = tid >> 2, ek = (tid & 3) << 3;     // ep: 64 rows x 32 k, 8 floats/thr
    for (int k0 = 0; k0 < D_; k0 += 32) {
        float2 hv = *(const float2*)(hpb + (size_t)ht*D_ + k0 + hk);
        hps[hk][ht] = hv.x; hps[hk+1][ht] = hv.y;
        float4 e0v = *(const float4*)(epb + (size_t)es*D_ + k0 + ek);
        float4 e1v = *(const float4*)(epb + (size_t)es*D_ + k0 + ek + 4);
        eps[ek+0][es]=e0v.x; eps[ek+1][es]=e0v.y; eps[ek+2][es]=e0v.z; eps[ek+3][es]=e0v.w;
        eps[ek+4][es]=e1v.x; eps[ek+5][es]=e1v.y; eps[ek+6][es]=e1v.z; eps[ek+7][es]=e1v.w;
        if (tid < 32) wvs[tid] = wv[k0 + tid];
        __syncthreads();
        #pragma unroll
        for (int k = 0; k < 32; k++) {
            float w  = wvs[k];
            float h0 = hps[k][ty], h1 = hps[k][ty+8];
            float e0 = eps[k][sx], e1 = eps[k][sx+32];
            a00 = fmaf(w, tanh_fast(h0+e0), a00);
            a01 = fmaf(w, tanh_fast(h0+e1), a01);
            a10 = fmaf(w, tanh_fast(h1+e0), a10);
            a11 = fmaf(w, tanh_fast(h1+e1), a11);
        }
        __syncthreads();
    }
    float bb  = bv[0];
    float mv0 = mask[(size_t)b*S_ + s0 + sx];
    float mv1 = mask[(size_t)b*S_ + s0 + sx + 32];
    size_t r0 = (size_t)(b*T_ + t0 + ty)     * S_ + s0;
    size_t r1 = (size_t)(b*T_ + t0 + ty + 8) * S_ + s0;
    en[r0 + sx]      = (a00 + bb) * mv0;
    en[r0 + sx + 32] = (a01 + bb) * mv1;
    en[r1 + sx]      = (a10 + bb) * mv0;
    en[r1 + sx + 32] = (a11 + bb) * mv1;
}

// ---------------------------------------------------------------------------
// masked softmax over S per (b,t) row: x=e*m; ex=exp(x-max); ex*=m; /(sum+1e-6)
// ---------------------------------------------------------------------------
__global__ void softmax_kernel(const float* __restrict__ en,
                               const float* __restrict__ mask,
                               float* __restrict__ attn)
{
    int r = blockIdx.x;                 // b*T + t
    int b = r >> 7;                     // / T_
    const float* e = en + (size_t)r * S_;
    const float* m = mask + (size_t)b * S_;
    int tid = threadIdx.x;              // 256 threads, 2 elems each
    float m0v = m[tid], m1v = m[tid + 256];
    float x0 = e[tid] * m0v, x1 = e[tid + 256] * m1v;
    float mx = fmaxf(x0, x1);
    #pragma unroll
    for (int o = 16; o; o >>= 1) mx = fmaxf(mx, __shfl_xor_sync(0xffffffffu, mx, o));
    __shared__ float red[8];
    int w = tid >> 5, l = tid & 31;
    if (l == 0) red[w] = mx;
    __syncthreads();
    mx = red[0];
    #pragma unroll
    for (int i = 1; i < 8; i++) mx = fmaxf(mx, red[i]);
    float e0 = __expf(x0 - mx) * m0v;
    float e1 = __expf(x1 - mx) * m1v;
    float s = e0 + e1;
    #pragma unroll
    for (int o = 16; o; o >>= 1) s += __shfl_xor_sync(0xffffffffu, s, o);
    __syncthreads();
    if (l == 0) red[w] = s;
    __syncthreads();
    float tot = 0.f;
    #pragma unroll
    for (int i = 0; i < 8; i++) tot += red[i];
    float inv = 1.0f / (tot + 1e-6f);
    attn[(size_t)r * S_ + tid]       = e0 * inv;
    attn[(size_t)r * S_ + tid + 256] = e1 * inv;
}

// ---------------------------------------------------------------------------
extern "C" void kernel_launch(void* const* d_in, const int* in_sizes, int n_in,
                              void* d_out, int out_size)
{
    const float* hidden = (const float*)d_in[0];
    const float* enc    = (const float*)d_in[1];
    const float* mask   = (const float*)d_in[2];
    const float* W_attn = (const float*)d_in[3];
    const float* b_attn = (const float*)d_in[4];
    const float* W_v    = (const float*)d_in[5];
    const float* b_v    = (const float*)d_in[6];
    const float* W_out  = (const float*)d_in[7];

    float* out     = (float*)d_out;
    float* h_tilde = out;                         // B*T*D
    float* wc      = out + (size_t)B_*T_*D_;      // B*T*E
    float* attn    = wc  + (size_t)B_*T_*E_;      // B*T*S

    float *hp, *ep, *en;
    cudaGetSymbolAddress((void**)&hp, g_hp);
    cudaGetSymbolAddress((void**)&ep, g_ep);
    cudaGetSymbolAddress((void**)&en, g_en);

    dim3 blk(256);
    // hp = hidden @ W_h^T + b_attn
    gemm_nt_kernel<<<dim3(B_*T_/64, D_/64), blk>>>(hidden, hidden, 1<<28, D_,
                                                   W_attn, E_+D_, b_attn,
                                                   hp, D_, D_, 0);
    // ep = encoder @ W_e^T
    gemm_nt_kernel<<<dim3(B_*S_/64, D_/64), blk>>>(enc, enc, 1<<28, E_,
                                                   W_attn + D_, E_+D_, nullptr,
                                                   ep, D_, E_, 0);
    // energies
    energies_kernel<<<dim3(S_/64, T_/16, B_), blk>>>(hp, ep, W_v, b_v, mask, en);
    // masked softmax -> attn (output region 3)
    softmax_kernel<<<dim3(B_*T_), blk>>>(en, mask, attn);
    // weighted_context = attn @ encoder (output region 2)
    gemm_nn_kernel<<<dim3(T_/64, E_/64, B_), blk>>>(attn, T_*S_, S_,
                                                    enc, S_*E_, E_,
                                                    wc, T_*E_, E_, S_);
    // h_tilde = tanh(concat(wc, hidden) @ W_out^T) (output region 1)
    gemm_nt_kernel<<<dim3(B_*T_/64, D_/64), blk>>>(wc, hidden, E_, E_,
                                                   W_out, E_+D_, nullptr,
                                                   h_tilde, D_, E_+D_, 1);
}

// round 4
// speedup vs baseline: 1.4146x; 1.4146x over previous
#include <cuda_runtime.h>
#include <cuda_bf16.h>
#include <cstdint>

#define B_ 8
#define T_ 128
#define S_ 512
#define E_ 512
#define D_ 512

// ---------------- scratch (no allocs allowed) ----------------
__device__ __align__(256) float g_hp[B_*T_*D_];
__device__ __align__(256) float g_ep[B_*S_*D_];
__device__ __align__(256) float g_en[B_*T_*S_];

__device__ __align__(256) __nv_bfloat16 g_hid_h[B_*T_*D_],  g_hid_l[B_*T_*D_];
__device__ __align__(256) __nv_bfloat16 g_enc_h[B_*S_*E_],  g_enc_l[B_*S_*E_];
__device__ __align__(256) __nv_bfloat16 g_encT_h[B_*E_*S_], g_encT_l[B_*E_*S_];
__device__ __align__(256) __nv_bfloat16 g_Wa_h[D_*(E_+D_)], g_Wa_l[D_*(E_+D_)];
__device__ __align__(256) __nv_bfloat16 g_Wo_h[D_*(E_+D_)], g_Wo_l[D_*(E_+D_)];
__device__ __align__(256) __nv_bfloat16 g_attn_h[B_*T_*S_], g_attn_l[B_*T_*S_];
__device__ __align__(256) __nv_bfloat16 g_wc_h[B_*T_*E_],   g_wc_l[B_*T_*E_];

__device__ __forceinline__ float tanh_fast(float x){
    float r; asm("tanh.approx.f32 %0, %1;" : "=f"(r) : "f"(x)); return r;
}
__device__ __forceinline__ uint32_t smem_u32(const void* p){
    uint32_t a;
    asm("{ .reg .u64 t; cvta.to.shared.u64 t, %1; cvt.u32.u64 %0, t; }" : "=r"(a) : "l"(p));
    return a;
}
__device__ __forceinline__ void cp16(uint32_t dst, const void* src){
    asm volatile("cp.async.cg.shared.global [%0], [%1], 16;" :: "r"(dst), "l"(src));
}
#define CP_COMMIT() asm volatile("cp.async.commit_group;" ::: "memory")
#define CP_WAIT(n)  asm volatile("cp.async.wait_group %0;" :: "n"(n) : "memory")

#define LDSM4(r, addr) \
    asm volatile("ldmatrix.sync.aligned.m8n8.x4.shared.b16 {%0,%1,%2,%3}, [%4];" \
        : "=r"((r)[0]), "=r"((r)[1]), "=r"((r)[2]), "=r"((r)[3]) : "r"(addr))

#define MMA16816(c, a, b0, b1) \
    asm volatile("mma.sync.aligned.m16n8k16.row.col.f32.bf16.bf16.f32 " \
        "{%0,%1,%2,%3}, {%4,%5,%6,%7}, {%8,%9}, {%0,%1,%2,%3};" \
        : "+f"((c)[0]), "+f"((c)[1]), "+f"((c)[2]), "+f"((c)[3]) \
        : "r"((a)[0]), "r"((a)[1]), "r"((a)[2]), "r"((a)[3]), "r"(b0), "r"(b1))

// ---------------- fp32 -> bf16(hi,lo) split ----------------
__global__ void split_kernel(const float* __restrict__ x,
                             __nv_bfloat16* __restrict__ hi,
                             __nv_bfloat16* __restrict__ lo, int n)
{
    int i = (blockIdx.x * 256 + threadIdx.x) * 4;
    if (i >= n) return;
    float4 v = *(const float4*)(x + i);
    float vv[4] = {v.x, v.y, v.z, v.w};
    __nv_bfloat16 h[4], l[4];
    #pragma unroll
    for (int j = 0; j < 4; j++){
        h[j] = __float2bfloat16_rn(vv[j]);
        l[j] = __float2bfloat16_rn(vv[j] - __bfloat162float(h[j]));
    }
    *(ushort4*)(hi + i) = *(ushort4*)h;
    *(ushort4*)(lo + i) = *(ushort4*)l;
}

// ---------------- enc [b,s,e] -> encT [b,e,s] with split ----------------
__global__ void transpose_split_kernel(const float* __restrict__ enc,
                                       __nv_bfloat16* __restrict__ th,
                                       __nv_bfloat16* __restrict__ tl)
{
    __shared__ float tile[32][33];
    int b = blockIdx.z, s0 = blockIdx.x * 32, e0 = blockIdx.y * 32;
    const float* src = enc + ((size_t)b * S_ + s0) * E_ + e0;
    for (int i = threadIdx.y; i < 32; i += 8)
        tile[i][threadIdx.x] = src[(size_t)i * E_ + threadIdx.x];
    __syncthreads();
    for (int i = threadIdx.y; i < 32; i += 8){
        float v = tile[threadIdx.x][i];
        __nv_bfloat16 h = __float2bfloat16_rn(v);
        __nv_bfloat16 l = __float2bfloat16_rn(v - __bfloat162float(h));
        size_t o = ((size_t)b * E_ + e0 + i) * S_ + s0 + threadIdx.x;
        th[o] = h; tl[o] = l;
    }
}

// ---------------------------------------------------------------------------
// HMMA bf16-split GEMM (NT): C[z][m,n] = act( sum_k A[z][m,k]*B[z][n,k] + bias[n] )
// A = (hi,lo); k < splitK from A0 else A1. C += Ah*Bh + Ah*Bl + Al*Bh (fp32 acc).
// CTA tile 128x64, BK=32, 8 warps (4m x 2n), cp.async double-buffered SMEM.
// SMEM rows: 32 bf16 payload, 80B stride (conflict-free LDSM partition).
// ---------------------------------------------------------------------------
#define RS      80                       // row stride bytes
#define OFF_AH  0
#define OFF_AL  (128*RS)
#define OFF_BH  (256*RS)
#define OFF_BL  (320*RS)
#define STAGE_B (384*RS)                 // 30720 B
#define GSMEM   (2*STAGE_B)              // 61440 B

__device__ __forceinline__ void fill_stage(uint32_t st,
    const __nv_bfloat16* ah, const __nv_bfloat16* al, int lda,
    const __nv_bfloat16* bh, const __nv_bfloat16* bl, int ldb, int tid)
{
    #pragma unroll
    for (int j = 0; j < 6; j++){
        int i = tid + j * 256;
        if (i < 512){
            int r = i >> 2, s = i & 3;
            cp16(st + OFF_AH + r*RS + s*16, ah + (size_t)r*lda + s*8);
        } else if (i < 1024){
            int i2 = i - 512, r = i2 >> 2, s = i2 & 3;
            cp16(st + OFF_AL + r*RS + s*16, al + (size_t)r*lda + s*8);
        } else if (i < 1280){
            int i2 = i - 1024, r = i2 >> 2, s = i2 & 3;
            cp16(st + OFF_BH + r*RS + s*16, bh + (size_t)r*ldb + s*8);
        } else {
            int i2 = i - 1280, r = i2 >> 2, s = i2 & 3;
            cp16(st + OFF_BL + r*RS + s*16, bl + (size_t)r*ldb + s*8);
        }
    }
    CP_COMMIT();
}

__global__ void __launch_bounds__(256)
gemm_mma_kernel(const __nv_bfloat16* __restrict__ Ah0, const __nv_bfloat16* __restrict__ Al0,
                const __nv_bfloat16* __restrict__ Ah1, const __nv_bfloat16* __restrict__ Al1,
                int splitK, int lda0, int lda1, long long sA,
                const __nv_bfloat16* __restrict__ Bh, const __nv_bfloat16* __restrict__ Bl,
                int ldb, long long sB,
                float* __restrict__ C, int ldc, long long sC,
                int K, const float* __restrict__ bias, int act)
{
    extern __shared__ __align__(16) char smem[];
    uint32_t sb = smem_u32(smem);
    int tid = threadIdx.x;
    int m0 = blockIdx.x * 128, n0 = blockIdx.y * 64, z = blockIdx.z;

    const __nv_bfloat16* bhz = Bh + (size_t)z * sB + (size_t)n0 * ldb;
    const __nv_bfloat16* blz = Bl + (size_t)z * sB + (size_t)n0 * ldb;

    int wid = tid >> 5, lane = tid & 31;
    int wm = (wid & 3) * 32, wn = (wid >> 2) * 32;
    int quad = lane >> 3, lr = lane & 7;
    uint32_t a_off[2], b_off[2];
    #pragma unroll
    for (int mt = 0; mt < 2; mt++)
        a_off[mt] = (uint32_t)((wm + mt*16 + (quad & 1)*8 + lr) * RS + (quad >> 1)*16);
    #pragma unroll
    for (int p = 0; p < 2; p++)
        b_off[p]  = (uint32_t)((wn + p*16 + (quad >> 1)*8 + lr) * RS + (quad & 1)*16);

    float acc[2][4][4] = {};

    int C_chunks = K >> 5;
    // prologue: stage 0
    {
        const __nv_bfloat16 *ah, *al; int lda;
        if (0 < splitK){ ah = Ah0; al = Al0; lda = lda0; }
        else           { ah = Ah1; al = Al1; lda = lda1; }
        ah += (size_t)z*sA + (size_t)m0*lda;
        al += (size_t)z*sA + (size_t)m0*lda;
        fill_stage(sb, ah, al, lda, bhz, blz, ldb, tid);
    }

    for (int c = 0; c < C_chunks; c++){
        if (c + 1 < C_chunks){
            int k0 = (c + 1) << 5;
            const __nv_bfloat16 *ah, *al; int lda;
            if (k0 < splitK){ ah = Ah0; al = Al0; lda = lda0; }
            else            { ah = Ah1; al = Al1; lda = lda1; k0 -= splitK; }
            ah += (size_t)z*sA + (size_t)m0*lda + k0;
            al += (size_t)z*sA + (size_t)m0*lda + k0;
            fill_stage(sb + ((c + 1) & 1)*STAGE_B, ah, al, lda,
                       bhz + ((size_t)(c+1) << 5), blz + ((size_t)(c+1) << 5), ldb, tid);
            CP_WAIT(1);
        } else {
            CP_WAIT(0);
        }
        __syncthreads();

        uint32_t st = sb + (c & 1)*STAGE_B;
        #pragma unroll
        for (int ks = 0; ks < 2; ks++){
            uint32_t koff = ks * 32;
            uint32_t ah_[2][4], al_[2][4], bh_[2][4], bl_[2][4];
            #pragma unroll
            for (int mt = 0; mt < 2; mt++){
                LDSM4(ah_[mt], st + OFF_AH + a_off[mt] + koff);
                LDSM4(al_[mt], st + OFF_AL + a_off[mt] + koff);
            }
            #pragma unroll
            for (int p = 0; p < 2; p++){
                LDSM4(bh_[p], st + OFF_BH + b_off[p] + koff);
                LDSM4(bl_[p], st + OFF_BL + b_off[p] + koff);
            }
            #pragma unroll
            for (int mt = 0; mt < 2; mt++)
                #pragma unroll
                for (int nt = 0; nt < 4; nt++){
                    int p = nt >> 1, q = (nt & 1) * 2;
                    MMA16816(acc[mt][nt], ah_[mt], bh_[p][q], bh_[p][q+1]);
                    MMA16816(acc[mt][nt], ah_[mt], bl_[p][q], bl_[p][q+1]);
                    MMA16816(acc[mt][nt], al_[mt], bh_[p][q], bh_[p][q+1]);
                }
        }
        __syncthreads();
    }

    // epilogue
    float* Cz = C + (size_t)z * sC;
    #pragma unroll
    for (int mt = 0; mt < 2; mt++){
        int r = m0 + wm + mt*16 + (lane >> 2);
        #pragma unroll
        for (int nt = 0; nt < 4; nt++){
            int col = n0 + wn + nt*8 + (lane & 3)*2;
            float c0 = acc[mt][nt][0], c1 = acc[mt][nt][1];
            float c2 = acc[mt][nt][2], c3 = acc[mt][nt][3];
            if (bias){
                float bb0 = bias[col], bb1 = bias[col+1];
                c0 += bb0; c1 += bb1; c2 += bb0; c3 += bb1;
            }
            if (act){
                c0 = tanh_fast(c0); c1 = tanh_fast(c1);
                c2 = tanh_fast(c2); c3 = tanh_fast(c3);
            }
            *(float2*)(Cz + (size_t)r * ldc + col)       = make_float2(c0, c1);
            *(float2*)(Cz + (size_t)(r + 8) * ldc + col) = make_float2(c2, c3);
        }
    }
}

// ---------------------------------------------------------------------------
// energies[b,t,s] = ( sum_k W_v[k]*tanh(hp[b,t,k] + ep[b,s,k]) + b_v ) * m[b,s]
// ---------------------------------------------------------------------------
__global__ void energies_kernel(const float* __restrict__ hp,
                                const float* __restrict__ ep,
                                const float* __restrict__ wv,
                                const float* __restrict__ bv,
                                const float* __restrict__ mask,
                                float* __restrict__ en)
{
    __shared__ __align__(16) float hps[32][17];
    __shared__ __align__(16) float eps[32][65];
    __shared__ float wvs[32];
    int b = blockIdx.z, t0 = blockIdx.y * 16, s0 = blockIdx.x * 64;
    int tid = threadIdx.x;
    int sx = tid & 31, ty = tid >> 5;
    const float* hpb = hp + (size_t)(b*T_ + t0) * D_;
    const float* epb = ep + (size_t)(b*S_ + s0) * D_;
    float a00=0.f, a01=0.f, a10=0.f, a11=0.f;
    int ht = tid >> 4, hk = (tid & 15) << 1;
    int es = tid >> 2, ek = (tid & 3) << 3;
    for (int k0 = 0; k0 < D_; k0 += 32) {
        float2 hv = *(const float2*)(hpb + (size_t)ht*D_ + k0 + hk);
        hps[hk][ht] = hv.x; hps[hk+1][ht] = hv.y;
        float4 e0v = *(const float4*)(epb + (size_t)es*D_ + k0 + ek);
        float4 e1v = *(const float4*)(epb + (size_t)es*D_ + k0 + ek + 4);
        eps[ek+0][es]=e0v.x; eps[ek+1][es]=e0v.y; eps[ek+2][es]=e0v.z; eps[ek+3][es]=e0v.w;
        eps[ek+4][es]=e1v.x; eps[ek+5][es]=e1v.y; eps[ek+6][es]=e1v.z; eps[ek+7][es]=e1v.w;
        if (tid < 32) wvs[tid] = wv[k0 + tid];
        __syncthreads();
        #pragma unroll
        for (int k = 0; k < 32; k++) {
            float w  = wvs[k];
            float h0 = hps[k][ty], h1 = hps[k][ty+8];
            float e0 = eps[k][sx], e1 = eps[k][sx+32];
            a00 = fmaf(w, tanh_fast(h0+e0), a00);
            a01 = fmaf(w, tanh_fast(h0+e1), a01);
            a10 = fmaf(w, tanh_fast(h1+e0), a10);
            a11 = fmaf(w, tanh_fast(h1+e1), a11);
        }
        __syncthreads();
    }
    float bb  = bv[0];
    float mv0 = mask[(size_t)b*S_ + s0 + sx];
    float mv1 = mask[(size_t)b*S_ + s0 + sx + 32];
    size_t r0 = (size_t)(b*T_ + t0 + ty)     * S_ + s0;
    size_t r1 = (size_t)(b*T_ + t0 + ty + 8) * S_ + s0;
    en[r0 + sx]      = (a00 + bb) * mv0;
    en[r0 + sx + 32] = (a01 + bb) * mv1;
    en[r1 + sx]      = (a10 + bb) * mv0;
    en[r1 + sx + 32] = (a11 + bb) * mv1;
}

// ---------------------------------------------------------------------------
__global__ void softmax_kernel(const float* __restrict__ en,
                               const float* __restrict__ mask,
                               float* __restrict__ attn)
{
    int r = blockIdx.x;
    int b = r >> 7;
    const float* e = en + (size_t)r * S_;
    const float* m = mask + (size_t)b * S_;
    int tid = threadIdx.x;
    float m0v = m[tid], m1v = m[tid + 256];
    float x0 = e[tid] * m0v, x1 = e[tid + 256] * m1v;
    float mx = fmaxf(x0, x1);
    #pragma unroll
    for (int o = 16; o; o >>= 1) mx = fmaxf(mx, __shfl_xor_sync(0xffffffffu, mx, o));
    __shared__ float red[8];
    int w = tid >> 5, l = tid & 31;
    if (l == 0) red[w] = mx;
    __syncthreads();
    mx = red[0];
    #pragma unroll
    for (int i = 1; i < 8; i++) mx = fmaxf(mx, red[i]);
    float e0 = __expf(x0 - mx) * m0v;
    float e1 = __expf(x1 - mx) * m1v;
    float s = e0 + e1;
    #pragma unroll
    for (int o = 16; o; o >>= 1) s += __shfl_xor_sync(0xffffffffu, s, o);
    __syncthreads();
    if (l == 0) red[w] = s;
    __syncthreads();
    float tot = 0.f;
    #pragma unroll
    for (int i = 0; i < 8; i++) tot += red[i];
    float inv = 1.0f / (tot + 1e-6f);
    attn[(size_t)r * S_ + tid]       = e0 * inv;
    attn[(size_t)r * S_ + tid + 256] = e1 * inv;
}

// ---------------------------------------------------------------------------
extern "C" void kernel_launch(void* const* d_in, const int* in_sizes, int n_in,
                              void* d_out, int out_size)
{
    const float* hidden = (const float*)d_in[0];
    const float* enc    = (const float*)d_in[1];
    const float* mask   = (const float*)d_in[2];
    const float* W_attn = (const float*)d_in[3];
    const float* b_attn = (const float*)d_in[4];
    const float* W_v    = (const float*)d_in[5];
    const float* b_v    = (const float*)d_in[6];
    const float* W_out  = (const float*)d_in[7];

    float* out     = (float*)d_out;
    float* h_tilde = out;
    float* wc      = out + (size_t)B_*T_*D_;
    float* attn    = wc  + (size_t)B_*T_*E_;

    float *hp, *ep, *en;
    cudaGetSymbolAddress((void**)&hp, g_hp);
    cudaGetSymbolAddress((void**)&ep, g_ep);
    cudaGetSymbolAddress((void**)&en, g_en);
    __nv_bfloat16 *hid_h,*hid_l,*enc_h,*enc_l,*encT_h,*encT_l,*Wa_h,*Wa_l,*Wo_h,*Wo_l,*at_h,*at_l,*wc_h,*wc_l;
    cudaGetSymbolAddress((void**)&hid_h, g_hid_h);  cudaGetSymbolAddress((void**)&hid_l, g_hid_l);
    cudaGetSymbolAddress((void**)&enc_h, g_enc_h);  cudaGetSymbolAddress((void**)&enc_l, g_enc_l);
    cudaGetSymbolAddress((void**)&encT_h, g_encT_h);cudaGetSymbolAddress((void**)&encT_l, g_encT_l);
    cudaGetSymbolAddress((void**)&Wa_h, g_Wa_h);    cudaGetSymbolAddress((void**)&Wa_l, g_Wa_l);
    cudaGetSymbolAddress((void**)&Wo_h, g_Wo_h);    cudaGetSymbolAddress((void**)&Wo_l, g_Wo_l);
    cudaGetSymbolAddress((void**)&at_h, g_attn_h);  cudaGetSymbolAddress((void**)&at_l, g_attn_l);
    cudaGetSymbolAddress((void**)&wc_h, g_wc_h);    cudaGetSymbolAddress((void**)&wc_l, g_wc_l);

    cudaFuncSetAttribute(gemm_mma_kernel, cudaFuncAttributeMaxDynamicSharedMemorySize, GSMEM);

    dim3 blk(256);
    // splits
    split_kernel<<<(B_*T_*D_)/1024, blk>>>(hidden, hid_h, hid_l, B_*T_*D_);
    split_kernel<<<(B_*S_*E_)/1024, blk>>>(enc, enc_h, enc_l, B_*S_*E_);
    split_kernel<<<(D_*(E_+D_))/1024, blk>>>(W_attn, Wa_h, Wa_l, D_*(E_+D_));
    split_kernel<<<(D_*(E_+D_))/1024, blk>>>(W_out, Wo_h, Wo_l, D_*(E_+D_));
    transpose_split_kernel<<<dim3(S_/32, E_/32, B_), dim3(32,8)>>>(enc, encT_h, encT_l);

    // hp = hidden @ W_h^T + b_attn   (M=1024, N=512, K=512)
    gemm_mma_kernel<<<dim3(8,8,1), blk, GSMEM>>>(
        hid_h, hid_l, hid_h, hid_l, 1<<28, D_, D_, 0,
        Wa_h, Wa_l, E_+D_, 0, hp, D_, 0, D_, b_attn, 0);
    // ep = enc @ W_e^T               (M=4096, N=512, K=512)
    gemm_mma_kernel<<<dim3(32,8,1), blk, GSMEM>>>(
        enc_h, enc_l, enc_h, enc_l, 1<<28, E_, E_, 0,
        Wa_h + D_, Wa_l + D_, E_+D_, 0, ep, D_, 0, E_, nullptr, 0);
    // energies
    energies_kernel<<<dim3(S_/64, T_/16, B_), blk>>>(hp, ep, W_v, b_v, mask, en);
    // softmax -> attn
    softmax_kernel<<<dim3(B_*T_), blk>>>(en, mask, attn);
    // split attn
    split_kernel<<<(B_*T_*S_)/1024, blk>>>(attn, at_h, at_l, B_*T_*S_);
    // wc[b] = attn[b] @ encT[b]^T    (batched, M=128, N=512, K=512)
    gemm_mma_kernel<<<dim3(1,8,B_), blk, GSMEM>>>(
        at_h, at_l, at_h, at_l, 1<<28, S_, S_, (long long)T_*S_,
        encT_h, encT_l, S_, (long long)E_*S_, wc, E_, (long long)T_*E_, S_, nullptr, 0);
    // split wc
    split_kernel<<<(B_*T_*E_)/1024, blk>>>(wc, wc_h, wc_l, B_*T_*E_);
    // h_tilde = tanh(concat(wc, hidden) @ W_out^T)  (M=1024, N=512, K=1024)
    gemm_mma_kernel<<<dim3(8,8,1), blk, GSMEM>>>(
        wc_h, wc_l, hid_h, hid_l, E_, E_, D_, 0,
        Wo_h, Wo_l, E_+D_, 0, h_tilde, D_, 0, E_+D_, nullptr, 1);
}